// round 15
// baseline (speedup 1.0000x reference)
#include <cuda_runtime.h>
#include <cuda_bf16.h>
#include <cstdint>

#define N_BATCH 8
#define NN      2048
#define DF      128
#define NF      128
#define A_ELEMS (N_BATCH * NN * NN)   /* 33554432 */
#define H_OFF   A_ELEMS
#define ROWTILES 32

// ---------------- scratch (no allocations allowed) ----------------
__device__ float g_dpart[ROWTILES * N_BATCH * NN];
__device__ float g_dr[N_BATCH * NN];
__device__ float          g_Xs   [N_BATCH * NN * DF];  // dr[j]*X[j,:]  (f32, epilogue)
__device__ __nv_bfloat16  g_Xsh  [N_BATCH * NN * DF];  // hi part (B operand)
__device__ __nv_bfloat16  g_Xsl  [N_BATCH * NN * DF];  // lo part
__device__ __nv_bfloat16  g_Whi[DF * NF];
__device__ __nv_bfloat16  g_Wlo[DF * NF];

// ---------------- helpers ----------------
__device__ __forceinline__ uint32_t smem_u32(const void* p) {
    uint32_t a;
    asm("{ .reg .u64 t; cvta.to.shared.u64 t, %1; cvt.u32.u64 %0, t; }" : "=r"(a) : "l"(p));
    return a;
}
__device__ __forceinline__ uint32_t bf2_bits(__nv_bfloat162 h) {
    return *reinterpret_cast<uint32_t*>(&h);
}
__device__ __forceinline__ void split4(float4 v, uint2& whi, uint2& wlo) {
    __nv_bfloat162 h01 = __floats2bfloat162_rn(v.x, v.y);
    __nv_bfloat162 h23 = __floats2bfloat162_rn(v.z, v.w);
    float2 f01 = __bfloat1622float2(h01);
    float2 f23 = __bfloat1622float2(h23);
    __nv_bfloat162 l01 = __floats2bfloat162_rn(v.x - f01.x, v.y - f01.y);
    __nv_bfloat162 l23 = __floats2bfloat162_rn(v.z - f23.x, v.w - f23.y);
    whi.x = bf2_bits(h01); whi.y = bf2_bits(h23);
    wlo.x = bf2_bits(l01); wlo.y = bf2_bits(l23);
}

#define LDSM4(r, a)                                                          \
    asm volatile("ldmatrix.sync.aligned.m8n8.x4.shared.b16 {%0,%1,%2,%3}, [%4];" \
        : "=r"((r)[0]), "=r"((r)[1]), "=r"((r)[2]), "=r"((r)[3]) : "r"(a))
#define LDSM4T(r, a)                                                         \
    asm volatile("ldmatrix.sync.aligned.m8n8.x4.trans.shared.b16 {%0,%1,%2,%3}, [%4];" \
        : "=r"((r)[0]), "=r"((r)[1]), "=r"((r)[2]), "=r"((r)[3]) : "r"(a))
#define MMA16816(d, a, b0, b1)                                               \
    asm volatile("mma.sync.aligned.m16n8k16.row.col.f32.bf16.bf16.f32 "      \
        "{%0,%1,%2,%3},{%4,%5,%6,%7},{%8,%9},{%0,%1,%2,%3};"                 \
        : "+f"((d)[0]), "+f"((d)[1]), "+f"((d)[2]), "+f"((d)[3])             \
        : "r"((a)[0]), "r"((a)[1]), "r"((a)[2]), "r"((a)[3]), "r"(b0), "r"(b1))

// ============================================================================
// Kernel 0 (forked stream): pure copy A -> out. Fully independent work.
// ============================================================================
__global__ void __launch_bounds__(512) copy_kernel(
    const float* __restrict__ A, float* __restrict__ out)
{
    const int rt = blockIdx.x, b = blockIdx.y, t = threadIdx.x;
    const size_t base = (size_t)b * NN * NN + (size_t)rt * 64 * NN;
    const float4* A4 = (const float4*)(A + base);
    float4*       O4 = (float4*)(out + base);
#pragma unroll 8
    for (int r = 0; r < 64; r++)
        O4[r * (NN / 4) + t] = A4[r * (NN / 4) + t];
}

// ============================================================================
// Kernel 1: per-block partial column sums of A (read-only).
// ============================================================================
__global__ void __launch_bounds__(512) colsum_kernel(const float* __restrict__ A)
{
    const int rt = blockIdx.x, b = blockIdx.y, t = threadIdx.x;
    const size_t base = (size_t)b * NN * NN + (size_t)rt * 64 * NN;
    const float4* A4 = (const float4*)(A + base);

    float4 acc = make_float4(0.f, 0.f, 0.f, 0.f);
#pragma unroll 8
    for (int r = 0; r < 64; r++) {
        float4 v = A4[r * (NN / 4) + t];
        acc.x += v.x; acc.y += v.y; acc.z += v.z; acc.w += v.w;
    }
    ((float4*)(g_dpart + (size_t)rt * (N_BATCH * NN) + (size_t)b * NN))[t] = acc;
}

// ============================================================================
// Kernel 2: dr = rsqrt(1 + colsum); Xs = dr[j]*X[j,:]  (f32 + bf16 hi/lo).
// Blocks 0..127 additionally convert one row of W to bf16 hi/lo.
// ============================================================================
__global__ void __launch_bounds__(128) finalize_kernel(const float* __restrict__ X,
                                                       const float* __restrict__ W)
{
    const int col = blockIdx.x;
    const int t   = threadIdx.x;
    float s = 1.0f;
#pragma unroll
    for (int rt = 0; rt < ROWTILES; rt++)
        s += g_dpart[rt * (N_BATCH * NN) + col];
    s = rsqrtf(s);
    if (t == 0) g_dr[col] = s;
    float v = s * X[(size_t)col * DF + t];
    g_Xs[(size_t)col * DF + t] = v;
    __nv_bfloat16 hi = __float2bfloat16_rn(v);
    g_Xsh[(size_t)col * DF + t] = hi;
    g_Xsl[(size_t)col * DF + t] = __float2bfloat16_rn(v - __bfloat162float(hi));

    if (col < DF) {                       // fold W conversion (16384 elems)
        int i = col * NF + t;
        float w = W[i];
        __nv_bfloat16 whi = __float2bfloat16_rn(w);
        g_Whi[i] = whi;
        g_Wlo[i] = __float2bfloat16_rn(w - __bfloat162float(whi));
    }
}

// ============================================================================
// Kernel 3: FUSED gemm1+gemm2, split-bf16 3-MMA (proven R12 body, no copy).
// ============================================================================
#define BK      32
#define NCH     (NN / BK)                 /* 64 */
#define PA_B    80                        /* A tile row stride, bytes */
#define PB_B    272                       /* B tile row stride, bytes */
#define SZ_A    (128 * PA_B)              /* 10240 */
#define SZ_B    (BK * PB_B)               /* 8704  */
#define STG     (2 * SZ_A + 2 * SZ_B)     /* per-stage: Ahi,Alo,Bhi,Blo = 37888 */
#define SZ_D    (128 * 272)               /* 34816: D tile (reuses stage region) */
#define OFF_W   (2 * STG)                 /* 75776 */
#define SM1_TOT (2 * STG + 2 * SZ_D)      /* 145408 */

__global__ void __launch_bounds__(256) gemm_fused_kernel(const float* __restrict__ A,
                                                         float* __restrict__ out)
{
    extern __shared__ __align__(16) char sm[];

    const int t = threadIdx.x;
    const int lane = t & 31, wid = t >> 5;
    const int wm = wid & 3, wn = wid >> 2;      // warp tile: 32 M x 64 N
    const int b = blockIdx.y, i0 = blockIdx.x * 128;

    const float* Ab = A + (size_t)b * NN * NN + (size_t)i0 * NN;
    const __nv_bfloat16* Bhi = g_Xsh + (size_t)b * NN * DF;
    const __nv_bfloat16* Blo = g_Xsl + (size_t)b * NN * DF;

    const uint32_t sbase = smem_u32(sm);
    const int lrow  = lane & 15;
    const int lcol8 = (lane >> 4) * 8;

    float acc[2][8][4];
#pragma unroll
    for (int mi = 0; mi < 2; mi++)
#pragma unroll
        for (int ni = 0; ni < 8; ni++)
#pragma unroll
            for (int q = 0; q < 4; q++) acc[mi][ni][q] = 0.f;

    // ---- stage chunk 0 + W tiles ----
    {
#pragma unroll
        for (int i = 0; i < 4; i++) {
            int idx = t + i * 256, row = idx >> 3, c4 = idx & 7;
            float4 v = *(const float4*)(Ab + (size_t)row * NN + c4 * 4);
            uint2 whi, wlo; split4(v, whi, wlo);
            *(uint2*)(sm + row * PA_B + c4 * 8)        = whi;
            *(uint2*)(sm + SZ_A + row * PA_B + c4 * 8) = wlo;
        }
#pragma unroll
        for (int i = 0; i < 2; i++) {
            int idx = t + i * 256, row = idx >> 4, cc = idx & 15;
            *(uint4*)(sm + 2 * SZ_A + row * PB_B + cc * 16) =
                *(const uint4*)(Bhi + (size_t)row * DF + cc * 8);
            *(uint4*)(sm + 2 * SZ_A + SZ_B + row * PB_B + cc * 16) =
                *(const uint4*)(Blo + (size_t)row * DF + cc * 8);
        }
        // W hi/lo: 128 rows x 16 x 16B each
#pragma unroll
        for (int i = 0; i < 8; i++) {
            int idx = t + i * 256, row = idx >> 4, cc = idx & 15;
            size_t wo = (size_t)row * NF + cc * 8;
            *(uint4*)(sm + OFF_W + row * 272 + cc * 16)        = *(const uint4*)(g_Whi + wo);
            *(uint4*)(sm + OFF_W + SZ_D + row * 272 + cc * 16) = *(const uint4*)(g_Wlo + wo);
        }
    }
    __syncthreads();

    float4 ra[4];
    uint4  rbh[2], rbl[2];

    for (int c = 0; c < NCH; c++) {
        const int st = c & 1;
        if (c + 1 < NCH) {
            const float* Asrc = Ab + (c + 1) * BK;
#pragma unroll
            for (int i = 0; i < 4; i++) {
                int idx = t + i * 256, row = idx >> 3, c4 = idx & 7;
                ra[i] = *(const float4*)(Asrc + (size_t)row * NN + c4 * 4);
            }
            const size_t boff = (size_t)(c + 1) * BK * DF;
#pragma unroll
            for (int i = 0; i < 2; i++) {
                int idx = t + i * 256, row = idx >> 4, cc = idx & 15;
                rbh[i] = *(const uint4*)(Bhi + boff + (size_t)row * DF + cc * 8);
                rbl[i] = *(const uint4*)(Blo + boff + (size_t)row * DF + cc * 8);
            }
        }
        // ---- compute on stage st ----
        const uint32_t sAh = sbase + st * STG;
        const uint32_t sAl = sAh + SZ_A;
        const uint32_t sBh = sAh + 2 * SZ_A;
        const uint32_t sBl = sBh + SZ_B;
#pragma unroll
        for (int ks = 0; ks < 2; ks++) {
            uint32_t ah[2][4], al[2][4], bh[4][4], bl[4][4];
            const uint32_t arow = (wm * 32 + lrow) * PA_B + (ks * 16 + lcol8) * 2;
#pragma unroll
            for (int mi = 0; mi < 2; mi++) {
                LDSM4(ah[mi], sAh + arow + mi * 16 * PA_B);
                LDSM4(al[mi], sAl + arow + mi * 16 * PA_B);
            }
            const uint32_t brow = (ks * 16 + lrow) * PB_B + (wn * 64 + lcol8) * 2;
#pragma unroll
            for (int ni = 0; ni < 4; ni++) {
                LDSM4T(bh[ni], sBh + brow + ni * 32);
                LDSM4T(bl[ni], sBl + brow + ni * 32);
            }
#pragma unroll
            for (int mi = 0; mi < 2; mi++)
#pragma unroll
                for (int ni = 0; ni < 4; ni++) {
                    MMA16816(acc[mi][ni * 2],     ah[mi], bh[ni][0], bh[ni][1]);
                    MMA16816(acc[mi][ni * 2 + 1], ah[mi], bh[ni][2], bh[ni][3]);
                    MMA16816(acc[mi][ni * 2],     ah[mi], bl[ni][0], bl[ni][1]);
                    MMA16816(acc[mi][ni * 2 + 1], ah[mi], bl[ni][2], bl[ni][3]);
                    MMA16816(acc[mi][ni * 2],     al[mi], bh[ni][0], bh[ni][1]);
                    MMA16816(acc[mi][ni * 2 + 1], al[mi], bh[ni][2], bh[ni][3]);
                }
        }
        // ---- store staged chunk c+1 ----
        if (c + 1 < NCH) {
            const int ns = (c + 1) & 1;
            char* dst = sm + ns * STG;
#pragma unroll
            for (int i = 0; i < 4; i++) {
                int idx = t + i * 256, row = idx >> 3, c4 = idx & 7;
                uint2 whi, wlo; split4(ra[i], whi, wlo);
                *(uint2*)(dst + row * PA_B + c4 * 8)        = whi;
                *(uint2*)(dst + SZ_A + row * PA_B + c4 * 8) = wlo;
            }
#pragma unroll
            for (int i = 0; i < 2; i++) {
                int idx = t + i * 256, row = idx >> 4, cc = idx & 15;
                *(uint4*)(dst + 2 * SZ_A + row * PB_B + cc * 16)        = rbh[i];
                *(uint4*)(dst + 2 * SZ_A + SZ_B + row * PB_B + cc * 16) = rbl[i];
            }
        }
        __syncthreads();
    }

    // ---- epilogue A: D = dr[i]*(acc + Xs[i,:]) -> hi/lo bf16 into SMEM ----
    const int g  = lane >> 2, tg = lane & 3;
#pragma unroll
    for (int mi = 0; mi < 2; mi++) {
#pragma unroll
        for (int rr = 0; rr < 2; rr++) {
            int rl = wm * 32 + mi * 16 + g + rr * 8;     // local row 0..127
            int r  = i0 + rl;
            float s = g_dr[b * NN + r];
            const float* Xrow = g_Xs + ((size_t)b * NN + r) * DF;
#pragma unroll
            for (int ni = 0; ni < 8; ni++) {
                int cb = wn * 64 + ni * 8 + tg * 2;
                float2 x = *(const float2*)(Xrow + cb);
                float v0 = s * (acc[mi][ni][rr * 2 + 0] + x.x);
                float v1 = s * (acc[mi][ni][rr * 2 + 1] + x.y);
                __nv_bfloat162 h = __floats2bfloat162_rn(v0, v1);
                float2 hf = __bfloat1622float2(h);
                __nv_bfloat162 l = __floats2bfloat162_rn(v0 - hf.x, v1 - hf.y);
                *(__nv_bfloat162*)(sm + rl * 272 + cb * 2)        = h;
                *(__nv_bfloat162*)(sm + SZ_D + rl * 272 + cb * 2) = l;
            }
        }
    }
    __syncthreads();

    // ---- epilogue B: H = relu(D @ W) (verified gemm2 body, K=128) ----
    float ac2[2][8][4];
#pragma unroll
    for (int mi = 0; mi < 2; mi++)
#pragma unroll
        for (int ni = 0; ni < 8; ni++)
#pragma unroll
            for (int q = 0; q < 4; q++) ac2[mi][ni][q] = 0.f;

#pragma unroll
    for (int ks = 0; ks < 8; ks++) {
        uint32_t ah[2][4], al[2][4], bh[4][4], bl[4][4];
        const uint32_t arow = (wm * 32 + lrow) * 272 + (ks * 16 + lcol8) * 2;
#pragma unroll
        for (int mi = 0; mi < 2; mi++) {
            LDSM4(ah[mi], sbase + arow + mi * 16 * 272);
            LDSM4(al[mi], sbase + SZ_D + arow + mi * 16 * 272);
        }
        const uint32_t brow = (ks * 16 + lrow) * 272 + (wn * 64 + lcol8) * 2;
#pragma unroll
        for (int ni = 0; ni < 4; ni++) {
            LDSM4T(bh[ni], sbase + OFF_W + brow + ni * 32);
            LDSM4T(bl[ni], sbase + OFF_W + SZ_D + brow + ni * 32);
        }
#pragma unroll
        for (int mi = 0; mi < 2; mi++)
#pragma unroll
            for (int ni = 0; ni < 4; ni++) {
                MMA16816(ac2[mi][ni * 2],     ah[mi], bh[ni][0], bh[ni][1]);
                MMA16816(ac2[mi][ni * 2 + 1], ah[mi], bh[ni][2], bh[ni][3]);
                MMA16816(ac2[mi][ni * 2],     ah[mi], bl[ni][0], bl[ni][1]);
                MMA16816(ac2[mi][ni * 2 + 1], ah[mi], bl[ni][2], bl[ni][3]);
                MMA16816(ac2[mi][ni * 2],     al[mi], bh[ni][0], bh[ni][1]);
                MMA16816(ac2[mi][ni * 2 + 1], al[mi], bh[ni][2], bh[ni][3]);
            }
    }

#pragma unroll
    for (int mi = 0; mi < 2; mi++) {
#pragma unroll
        for (int rr = 0; rr < 2; rr++) {
            int r = b * NN + i0 + wm * 32 + mi * 16 + g + rr * 8;
            float2* Orow = (float2*)(out + H_OFF + (size_t)r * NF);
#pragma unroll
            for (int ni = 0; ni < 8; ni++) {
                int cb = wn * 64 + ni * 8 + tg * 2;
                float2 o;
                o.x = fmaxf(ac2[mi][ni][rr * 2 + 0], 0.f);
                o.y = fmaxf(ac2[mi][ni][rr * 2 + 1], 0.f);
                Orow[cb >> 1] = o;
            }
        }
    }
}

// ============================================================================
extern "C" void kernel_launch(void* const* d_in, const int* in_sizes, int n_in,
                              void* d_out, int out_size)
{
    const float* A = (const float*)d_in[0];
    const float* X = (const float*)d_in[1];
    const float* W = (const float*)d_in[2];
    float* out = (float*)d_out;

    cudaFuncSetAttribute(gemm_fused_kernel,
                         cudaFuncAttributeMaxDynamicSharedMemorySize, SM1_TOT);

    // fork: independent A->out copy on a second stream (capturable fork-join)
    cudaStream_t s2;
    cudaStreamCreateWithFlags(&s2, cudaStreamNonBlocking);
    cudaEvent_t evFork, evJoin;
    cudaEventCreateWithFlags(&evFork, cudaEventDisableTiming);
    cudaEventCreateWithFlags(&evJoin, cudaEventDisableTiming);

    cudaEventRecord(evFork, 0);
    cudaStreamWaitEvent(s2, evFork, 0);
    copy_kernel<<<dim3(ROWTILES, N_BATCH), 512, 0, s2>>>(A, out);
    cudaEventRecord(evJoin, s2);

    // critical chain on the default stream
    colsum_kernel<<<dim3(ROWTILES, N_BATCH), 512>>>(A);
    finalize_kernel<<<N_BATCH * NN, 128>>>(X, W);
    gemm_fused_kernel<<<dim3(NN / 128, N_BATCH), 256, SM1_TOT>>>(A, out);

    cudaStreamWaitEvent(0, evJoin, 0);    // join before harness's capture end

    cudaEventDestroy(evFork);
    cudaEventDestroy(evJoin);
    cudaStreamDestroy(s2);
}

// round 16
// speedup vs baseline: 1.1771x; 1.1771x over previous
#include <cuda_runtime.h>
#include <cuda_fp16.h>
#include <cstdint>

#define N_BATCH 8
#define NN      2048
#define DF      128
#define NF      128
#define A_ELEMS (N_BATCH * NN * NN)   /* 33554432 */
#define H_OFF   A_ELEMS
#define ROWTILES 32

// ---------------- scratch (no allocations allowed) ----------------
__device__ float  g_dpart[ROWTILES * N_BATCH * NN];
__device__ float  g_dr[N_BATCH * NN];
__device__ float  g_Xs [N_BATCH * NN * DF];   // dr[j]*X[j,:]  (f32, epilogue)
__device__ __half g_Xsh[N_BATCH * NN * DF];   // fp16 (B operand, single)
__device__ __half g_Whi[DF * NF];             // W hi/lo fp16 (3-pass gemm2)
__device__ __half g_Wlo[DF * NF];

// ---------------- helpers ----------------
__device__ __forceinline__ uint32_t smem_u32(const void* p) {
    uint32_t a;
    asm("{ .reg .u64 t; cvta.to.shared.u64 t, %1; cvt.u32.u64 %0, t; }" : "=r"(a) : "l"(p));
    return a;
}
__device__ __forceinline__ uint32_t h2_bits(__half2 h) {
    return *reinterpret_cast<uint32_t*>(&h);
}
// f32x4 -> fp16x4 (packed uint2)
__device__ __forceinline__ void cvt4h(float4 v, uint2& w) {
    w.x = h2_bits(__floats2half2_rn(v.x, v.y));
    w.y = h2_bits(__floats2half2_rn(v.z, v.w));
}

#define LDSM4(r, a)                                                          \
    asm volatile("ldmatrix.sync.aligned.m8n8.x4.shared.b16 {%0,%1,%2,%3}, [%4];" \
        : "=r"((r)[0]), "=r"((r)[1]), "=r"((r)[2]), "=r"((r)[3]) : "r"(a))
#define LDSM4T(r, a)                                                         \
    asm volatile("ldmatrix.sync.aligned.m8n8.x4.trans.shared.b16 {%0,%1,%2,%3}, [%4];" \
        : "=r"((r)[0]), "=r"((r)[1]), "=r"((r)[2]), "=r"((r)[3]) : "r"(a))
#define MMAF16(d, a, b0, b1)                                                 \
    asm volatile("mma.sync.aligned.m16n8k16.row.col.f32.f16.f16.f32 "        \
        "{%0,%1,%2,%3},{%4,%5,%6,%7},{%8,%9},{%0,%1,%2,%3};"                 \
        : "+f"((d)[0]), "+f"((d)[1]), "+f"((d)[2]), "+f"((d)[3])             \
        : "r"((a)[0]), "r"((a)[1]), "r"((a)[2]), "r"((a)[3]), "r"(b0), "r"(b1))

// ============================================================================
// Kernel 1: per-block partial column sums of A (read-only).
// ============================================================================
__global__ void __launch_bounds__(512) colsum_kernel(const float* __restrict__ A)
{
    const int rt = blockIdx.x, b = blockIdx.y, t = threadIdx.x;
    const size_t base = (size_t)b * NN * NN + (size_t)rt * 64 * NN;
    const float4* A4 = (const float4*)(A + base);

    float4 acc = make_float4(0.f, 0.f, 0.f, 0.f);
#pragma unroll 8
    for (int r = 0; r < 64; r++) {
        float4 v = A4[r * (NN / 4) + t];
        acc.x += v.x; acc.y += v.y; acc.z += v.z; acc.w += v.w;
    }
    ((float4*)(g_dpart + (size_t)rt * (N_BATCH * NN) + (size_t)b * NN))[t] = acc;
}

// ============================================================================
// Kernel 2: dr = rsqrt(1 + colsum); Xs = dr[j]*X[j,:] (f32 + fp16).
// Blocks 0..127 additionally convert one row of W to fp16 hi/lo.
// ============================================================================
__global__ void __launch_bounds__(128) finalize_kernel(const float* __restrict__ X,
                                                       const float* __restrict__ W)
{
    const int col = blockIdx.x;
    const int t   = threadIdx.x;
    float s = 1.0f;
#pragma unroll
    for (int rt = 0; rt < ROWTILES; rt++)
        s += g_dpart[rt * (N_BATCH * NN) + col];
    s = rsqrtf(s);
    if (t == 0) g_dr[col] = s;
    float v = s * X[(size_t)col * DF + t];
    g_Xs [(size_t)col * DF + t] = v;
    g_Xsh[(size_t)col * DF + t] = __float2half_rn(v);

    if (col < DF) {                       // fold W conversion (16384 elems)
        int i = col * NF + t;
        float w = W[i];
        __half hi = __float2half_rn(w);
        g_Whi[i] = hi;
        g_Wlo[i] = __float2half_rn(w - __half2float(hi));
    }
}

// ============================================================================
// Kernel 3: FUSED gemm1+gemm2 + A copy.
// Mainloop: SINGLE-PASS fp16 mma (tile 128x128, K-chunk 32, 256 threads,
// 8 warps 4M x 2N, 2-stage reg-staged double buffer); A copy piggybacks on
// the staged registers (R13-proven).
// Epilogue: D = dr[i]*(acc + Xs[i,:]) split fp16 hi/lo -> SMEM, then
// H = relu(D @ W) with 3-pass split-fp16 (precision-preserving), -> out.
// ============================================================================
#define BK      32
#define NCH     (NN / BK)                 /* 64 */
#define PA_B    80                        /* A tile row stride, bytes (32 fp16 + pad) */
#define PB_B    272                       /* B tile row stride, bytes (128 fp16 + pad) */
#define SZ_A    (128 * PA_B)              /* 10240 */
#define SZ_B    (BK * PB_B)               /* 8704  */
#define STG     (SZ_A + SZ_B)             /* per-stage: A,B = 18944 */
#define SZ_D    (128 * 272)               /* 34816 */
#define OFF_W   (2 * STG)                 /* 37888: Whi, then Wlo */
#define OFF_DLO (OFF_W + 2 * SZ_D)        /* 107520 (Dhi reuses stage region @0) */
#define SM_TOT  (OFF_DLO + SZ_D)          /* 142336 */

__global__ void __launch_bounds__(256) gemm_fused_kernel(const float* __restrict__ A,
                                                         float* __restrict__ out)
{
    extern __shared__ __align__(16) char sm[];

    const int t = threadIdx.x;
    const int lane = t & 31, wid = t >> 5;
    const int wm = wid & 3, wn = wid >> 2;      // warp tile: 32 M x 64 N
    const int b = blockIdx.y, i0 = blockIdx.x * 128;

    const float* Ab = A   + (size_t)b * NN * NN + (size_t)i0 * NN;
    float*       Ob = out + (size_t)b * NN * NN + (size_t)i0 * NN;
    const __half* Bh = g_Xsh + (size_t)b * NN * DF;

    const uint32_t sbase = smem_u32(sm);
    const int lrow  = lane & 15;
    const int lcol8 = (lane >> 4) * 8;

    float acc[2][8][4];
#pragma unroll
    for (int mi = 0; mi < 2; mi++)
#pragma unroll
        for (int ni = 0; ni < 8; ni++)
#pragma unroll
            for (int q = 0; q < 4; q++) acc[mi][ni][q] = 0.f;

    // ---- stage chunk 0 (also copy to out) + W hi/lo tiles ----
    {
#pragma unroll
        for (int i = 0; i < 4; i++) {
            int idx = t + i * 256, row = idx >> 3, c4 = idx & 7;
            float4 v = *(const float4*)(Ab + (size_t)row * NN + c4 * 4);
            *(float4*)(Ob + (size_t)row * NN + c4 * 4) = v;
            uint2 w; cvt4h(v, w);
            *(uint2*)(sm + row * PA_B + c4 * 8) = w;
        }
#pragma unroll
        for (int i = 0; i < 2; i++) {
            int idx = t + i * 256, row = idx >> 4, cc = idx & 15;
            *(uint4*)(sm + SZ_A + row * PB_B + cc * 16) =
                *(const uint4*)(Bh + (size_t)row * DF + cc * 8);
        }
        // W hi/lo: 128 rows x 16 x 16B each
#pragma unroll
        for (int i = 0; i < 8; i++) {
            int idx = t + i * 256, row = idx >> 4, cc = idx & 15;
            size_t wo = (size_t)row * NF + cc * 8;
            *(uint4*)(sm + OFF_W + row * 272 + cc * 16)        = *(const uint4*)(g_Whi + wo);
            *(uint4*)(sm + OFF_W + SZ_D + row * 272 + cc * 16) = *(const uint4*)(g_Wlo + wo);
        }
    }
    __syncthreads();

    float4 ra[4];
    uint4  rb[2];

    for (int c = 0; c < NCH; c++) {
        const int st = c & 1;
        if (c + 1 < NCH) {
            const float* Asrc = Ab + (c + 1) * BK;
#pragma unroll
            for (int i = 0; i < 4; i++) {
                int idx = t + i * 256, row = idx >> 3, c4 = idx & 7;
                ra[i] = *(const float4*)(Asrc + (size_t)row * NN + c4 * 4);
            }
            const size_t boff = (size_t)(c + 1) * BK * DF;
#pragma unroll
            for (int i = 0; i < 2; i++) {
                int idx = t + i * 256, row = idx >> 4, cc = idx & 15;
                rb[i] = *(const uint4*)(Bh + boff + (size_t)row * DF + cc * 8);
            }
        }
        // ---- compute on stage st (single-pass fp16) ----
        const uint32_t sA = sbase + st * STG;
        const uint32_t sB = sA + SZ_A;
#pragma unroll
        for (int ks = 0; ks < 2; ks++) {
            uint32_t ah[2][4], bh[4][4];
            const uint32_t arow = (wm * 32 + lrow) * PA_B + (ks * 16 + lcol8) * 2;
#pragma unroll
            for (int mi = 0; mi < 2; mi++)
                LDSM4(ah[mi], sA + arow + mi * 16 * PA_B);
            const uint32_t brow = (ks * 16 + lrow) * PB_B + (wn * 64 + lcol8) * 2;
#pragma unroll
            for (int ni = 0; ni < 4; ni++)
                LDSM4T(bh[ni], sB + brow + ni * 32);
#pragma unroll
            for (int mi = 0; mi < 2; mi++)
#pragma unroll
                for (int ni = 0; ni < 4; ni++) {
                    MMAF16(acc[mi][ni * 2],     ah[mi], bh[ni][0], bh[ni][1]);
                    MMAF16(acc[mi][ni * 2 + 1], ah[mi], bh[ni][2], bh[ni][3]);
                }
        }
        // ---- store staged chunk c+1 (SMEM) and copy it to out ----
        if (c + 1 < NCH) {
            const int ns = (c + 1) & 1;
            char* dst = sm + ns * STG;
            float* Oc = Ob + (c + 1) * BK;
#pragma unroll
            for (int i = 0; i < 4; i++) {
                int idx = t + i * 256, row = idx >> 3, c4 = idx & 7;
                *(float4*)(Oc + (size_t)row * NN + c4 * 4) = ra[i];
                uint2 w; cvt4h(ra[i], w);
                *(uint2*)(dst + row * PA_B + c4 * 8) = w;
            }
#pragma unroll
            for (int i = 0; i < 2; i++) {
                int idx = t + i * 256, row = idx >> 4, cc = idx & 15;
                *(uint4*)(dst + SZ_A + row * PB_B + cc * 16) = rb[i];
            }
        }
        __syncthreads();
    }

    // ---- epilogue A: D = dr[i]*(acc + Xs[i,:]) -> fp16 hi/lo into SMEM ----
    // Dhi reuses stage region @0; Dlo at OFF_DLO.
    const int g  = lane >> 2, tg = lane & 3;
#pragma unroll
    for (int mi = 0; mi < 2; mi++) {
#pragma unroll
        for (int rr = 0; rr < 2; rr++) {
            int rl = wm * 32 + mi * 16 + g + rr * 8;     // local row 0..127
            int r  = i0 + rl;
            float s = g_dr[b * NN + r];
            const float* Xrow = g_Xs + ((size_t)b * NN + r) * DF;
#pragma unroll
            for (int ni = 0; ni < 8; ni++) {
                int cb = wn * 64 + ni * 8 + tg * 2;
                float2 x = *(const float2*)(Xrow + cb);
                float v0 = s * (acc[mi][ni][rr * 2 + 0] + x.x);
                float v1 = s * (acc[mi][ni][rr * 2 + 1] + x.y);
                __half2 h = __floats2half2_rn(v0, v1);
                float2 hf = __half22float2(h);
                __half2 l = __floats2half2_rn(v0 - hf.x, v1 - hf.y);
                *(__half2*)(sm + rl * 272 + cb * 2)           = h;
                *(__half2*)(sm + OFF_DLO + rl * 272 + cb * 2) = l;
            }
        }
    }
    __syncthreads();

    // ---- epilogue B: H = relu(D @ W), 3-pass split-fp16, K=128 ----
    float ac2[2][8][4];
#pragma unroll
    for (int mi = 0; mi < 2; mi++)
#pragma unroll
        for (int ni = 0; ni < 8; ni++)
#pragma unroll
            for (int q = 0; q < 4; q++) ac2[mi][ni][q] = 0.f;

#pragma unroll
    for (int ks = 0; ks < 8; ks++) {
        uint32_t ah[2][4], al[2][4], bh[4][4], bl[4][4];
        const uint32_t arow = (wm * 32 + lrow) * 272 + (ks * 16 + lcol8) * 2;
#pragma unroll
        for (int mi = 0; mi < 2; mi++) {
            LDSM4(ah[mi], sbase + arow + mi * 16 * 272);
            LDSM4(al[mi], sbase + OFF_DLO + arow + mi * 16 * 272);
        }
        const uint32_t brow = (ks * 16 + lrow) * 272 + (wn * 64 + lcol8) * 2;
#pragma unroll
        for (int ni = 0; ni < 4; ni++) {
            LDSM4T(bh[ni], sbase + OFF_W + brow + ni * 32);
            LDSM4T(bl[ni], sbase + OFF_W + SZ_D + brow + ni * 32);
        }
#pragma unroll
        for (int mi = 0; mi < 2; mi++)
#pragma unroll
            for (int ni = 0; ni < 4; ni++) {
                MMAF16(ac2[mi][ni * 2],     ah[mi], bh[ni][0], bh[ni][1]);
                MMAF16(ac2[mi][ni * 2 + 1], ah[mi], bh[ni][2], bh[ni][3]);
                MMAF16(ac2[mi][ni * 2],     ah[mi], bl[ni][0], bl[ni][1]);
                MMAF16(ac2[mi][ni * 2 + 1], ah[mi], bl[ni][2], bl[ni][3]);
                MMAF16(ac2[mi][ni * 2],     al[mi], bh[ni][0], bh[ni][1]);
                MMAF16(ac2[mi][ni * 2 + 1], al[mi], bh[ni][2], bh[ni][3]);
            }
    }

#pragma unroll
    for (int mi = 0; mi < 2; mi++) {
#pragma unroll
        for (int rr = 0; rr < 2; rr++) {
            int r = b * NN + i0 + wm * 32 + mi * 16 + g + rr * 8;
            float2* Orow = (float2*)(out + H_OFF + (size_t)r * NF);
#pragma unroll
            for (int ni = 0; ni < 8; ni++) {
                int cb = wn * 64 + ni * 8 + tg * 2;
                float2 o;
                o.x = fmaxf(ac2[mi][ni][rr * 2 + 0], 0.f);
                o.y = fmaxf(ac2[mi][ni][rr * 2 + 1], 0.f);
                Orow[cb >> 1] = o;
            }
        }
    }
}

// ============================================================================
extern "C" void kernel_launch(void* const* d_in, const int* in_sizes, int n_in,
                              void* d_out, int out_size)
{
    const float* A = (const float*)d_in[0];
    const float* X = (const float*)d_in[1];
    const float* W = (const float*)d_in[2];
    float* out = (float*)d_out;

    cudaFuncSetAttribute(gemm_fused_kernel,
                         cudaFuncAttributeMaxDynamicSharedMemorySize, SM_TOT);

    colsum_kernel<<<dim3(ROWTILES, N_BATCH), 512>>>(A);
    finalize_kernel<<<N_BATCH * NN, 128>>>(X, W);
    gemm_fused_kernel<<<dim3(NN / 128, N_BATCH), 256, SM_TOT>>>(A, out);
}